// round 6
// baseline (speedup 1.0000x reference)
#include <cuda_runtime.h>
#include <cstdint>
#include <cstddef>

#define D 128
#define NMAX 100000

// ---------------- static device scratch (no dynamic allocs allowed) -------
__device__ float g_agg[(size_t)NMAX * D];
__device__ float g_agg2[(size_t)NMAX * D];
__device__ float g_jump[(size_t)NMAX * D];
__device__ float g_h[(size_t)NMAX * D];
__device__ float g_deg[NMAX];

// ---------------- helpers -------------------------------------------------
__device__ __forceinline__ void red4(float* p, float4 v) {
    asm volatile("red.global.add.v4.f32 [%0], {%1,%2,%3,%4};"
                 :: "l"(p), "f"(v.x), "f"(v.y), "f"(v.z), "f"(v.w) : "memory");
}

// L2-only load (bypass L1) — keeps L1 free for the small rel table
__device__ __forceinline__ float4 ldcg4(const float* p) {
    float4 v;
    asm volatile("ld.global.cg.v4.f32 {%0,%1,%2,%3}, [%4];"
                 : "=f"(v.x), "=f"(v.y), "=f"(v.z), "=f"(v.w) : "l"(p));
    return v;
}

__device__ __forceinline__ float tanh_fast(float x) {
    float y;
    asm("tanh.approx.f32 %0, %1;" : "=f"(y) : "f"(x));
    return y;
}

__device__ __forceinline__ uint32_t bf16x2(float lo, float hi) {
    uint32_t r;
    asm("cvt.rn.bf16x2.f32 %0, %1, %2;" : "=r"(r) : "f"(hi), "f"(lo));
    return r;
}

__device__ __forceinline__ void mma_bf16(float* c,
                                         uint32_t a0, uint32_t a1,
                                         uint32_t a2, uint32_t a3,
                                         uint32_t b0, uint32_t b1) {
    asm("mma.sync.aligned.m16n8k16.row.col.f32.bf16.bf16.f32 "
        "{%0,%1,%2,%3}, {%4,%5,%6,%7}, {%8,%9}, {%0,%1,%2,%3};"
        : "+f"(c[0]), "+f"(c[1]), "+f"(c[2]), "+f"(c[3])
        : "r"(a0), "r"(a1), "r"(a2), "r"(a3), "r"(b0), "r"(b1));
}

// Permuted-k bf16 row store (16-k block = 32B: order [0,1,8,9,2,3,10,11,...])
__device__ __forceinline__ void store_bf16_quad(char* rowbase, int k, float4 v) {
    char* p = rowbase + ((k >> 4) * 32) + (((k & 7) >> 1) * 8) + (((k >> 3) & 1) * 4);
    *(uint32_t*)p       = bf16x2(v.x, v.y);
    *(uint32_t*)(p + 8) = bf16x2(v.z, v.w);
}

// ---------------- init: zero scratch + change passthrough -----------------
__global__ void init_kernel(float* __restrict__ agg, float* __restrict__ agg2,
                            float* __restrict__ jmp, float* __restrict__ deg,
                            float* __restrict__ out, const float* __restrict__ change,
                            int N)
{
    const size_t nd = (size_t)N * D;
    const size_t stride = (size_t)gridDim.x * blockDim.x * 4;
    const float4 z = make_float4(0.f, 0.f, 0.f, 0.f);
    for (size_t p = (size_t)(blockIdx.x * blockDim.x + threadIdx.x) * 4; p < nd; p += stride) {
        *(float4*)(agg + p)  = z;
        *(float4*)(agg2 + p) = z;
        *(float4*)(jmp + p)  = z;
        *(float4*)(out + p)  = *(const float4*)(change + p);
    }
    for (size_t p = (size_t)(blockIdx.x * blockDim.x + threadIdx.x) * 4; p < (size_t)N; p += stride)
        *(float4*)(deg + p) = z;
}

// ---------------- combined relational scatter + jump scatter --------------
// global edge id g in [0, E):       agg[dst] += x[src] * rel[etype]  (+deg)
// global edge id g in [E, E+EJ):    jmp[jdst] += ew[e] * xj[jsrc]
// Persistent warps, 32-edge batches with coalesced index loads + shfl.
__global__ void scatter_jump_kernel(const float* __restrict__ x,
                                    const float* __restrict__ rel,
                                    const int* __restrict__ ei,
                                    const int* __restrict__ et,
                                    float* __restrict__ agg,
                                    float* __restrict__ deg,
                                    int E,
                                    const float* __restrict__ xj,
                                    const float* __restrict__ ew,
                                    const int* __restrict__ ej,
                                    float* __restrict__ jmp,
                                    int EJ)
{
    const int lane  = threadIdx.x & 31;
    const int warp  = blockIdx.x * (blockDim.x >> 5) + (threadIdx.x >> 5);
    const int nwarp = gridDim.x * (blockDim.x >> 5);
    const int total = E + EJ;

    for (int base = warp * 32; base < total; base += nwarp * 32) {
        const int n = min(32, total - base);
        int s = 0, d = 0, t = 0;
        float w = 0.f;
        const int g = base + lane;
        if (lane < n) {
            if (g < E) {
                s = __ldg(ei + g);
                d = __ldg(ei + E + g);
                t = __ldg(et + g);
            } else {
                int e = g - E;
                s = __ldg(ej + e);
                d = __ldg(ej + EJ + e);
                w = __ldg(ew + e);
            }
        }
        #pragma unroll 4
        for (int j = 0; j < n; j++) {
            const int   sj = __shfl_sync(0xFFFFFFFFu, s, j);
            const int   dj = __shfl_sync(0xFFFFFFFFu, d, j);
            const int   tj = __shfl_sync(0xFFFFFFFFu, t, j);
            const float wj = __shfl_sync(0xFFFFFFFFu, w, j);
            if (base + j < E) {              // warp-uniform branch
                float4 xv = ldcg4(x + (size_t)sj * D + lane * 4);
                float4 rv = *(const float4*)(rel + (size_t)tj * D + lane * 4);
                float4 m;
                m.x = xv.x * rv.x; m.y = xv.y * rv.y;
                m.z = xv.z * rv.z; m.w = xv.w * rv.w;
                red4(agg + (size_t)dj * D + lane * 4, m);
                if (deg != nullptr && lane == 0)
                    atomicAdd(deg + dj, 1.0f);
            } else {
                float4 xv = ldcg4(xj + (size_t)sj * D + lane * 4);
                float4 m;
                m.x = xv.x * wj; m.y = xv.y * wj;
                m.z = xv.z * wj; m.w = xv.w * wj;
                red4(jmp + (size_t)dj * D + lane * 4, m);
            }
        }
    }
}

// ---------------- tensor-core (mma.sync bf16) fused GEMM + epilogue -------
// out[r] = xb[r] + res * tanh( (agg[r]/max(deg,1)) @ W + xb[r] @ Wl )
//          [ + jw * jump[r]  when jump != null ]
#define NT 256
#define RSTR 288
#define SM_A  0
#define SM_BW (128 * RSTR)
#define SM_BL (2 * 128 * RSTR)
#define GEMM_SMEM (3 * 128 * RSTR)    // 110592 B -> 2 CTAs/SM

__global__ __launch_bounds__(NT, 2)
void gemm_mma_kernel(const float* __restrict__ agg,
                     const float* __restrict__ deg,
                     const float* __restrict__ xb,
                     const float* __restrict__ W,
                     const float* __restrict__ Wl,
                     const float* __restrict__ res_p,
                     const float* __restrict__ jump,
                     const float* __restrict__ jw_p,
                     float* __restrict__ out,
                     int N)
{
    extern __shared__ char smem[];
    char* As = smem + SM_A;
    char* Bw = smem + SM_BW;
    char* Bl = smem + SM_BL;

    const int t    = threadIdx.x;
    const int lane = t & 31;
    const int wid  = t >> 5;
    const int warp_m = wid & 3;
    const int warp_n = wid >> 2;

    // stage both weights transposed into perm-k bf16 layout (once)
    {
        const int n = t & 127;
        const float* wsrc = (t >> 7) ? Wl : W;
        char* brow = ((t >> 7) ? Bl : Bw) + n * RSTR;
        #pragma unroll 4
        for (int k = 0; k < 128; k += 4) {
            float4 v;
            v.x = __ldg(wsrc + (k + 0) * 128 + n);
            v.y = __ldg(wsrc + (k + 1) * 128 + n);
            v.z = __ldg(wsrc + (k + 2) * 128 + n);
            v.w = __ldg(wsrc + (k + 3) * 128 + n);
            store_bf16_quad(brow, k, v);
        }
    }
    const float res = __ldg(res_p);
    const float jw  = jump ? __ldg(jw_p) : 0.0f;
    __syncthreads();

    for (int row0 = blockIdx.x * 128; row0 < N; row0 += gridDim.x * 128) {
        float acc[2][8][4];
        #pragma unroll
        for (int mf = 0; mf < 2; mf++)
            #pragma unroll
            for (int nf = 0; nf < 8; nf++)
                #pragma unroll
                for (int j = 0; j < 4; j++) acc[mf][nf][j] = 0.0f;

        #pragma unroll 1
        for (int phase = 0; phase < 2; phase++) {
            __syncthreads();
            for (int i = t * 4; i < 128 * 128; i += NT * 4) {
                int m = i >> 7, k = i & 127;
                int row = row0 + m;
                float4 v = make_float4(0.f, 0.f, 0.f, 0.f);
                if (row < N) {
                    if (phase == 0) {
                        float inv = 1.0f / fmaxf(__ldg(deg + row), 1.0f);
                        v = *(const float4*)(agg + (size_t)row * D + k);
                        v.x *= inv; v.y *= inv; v.z *= inv; v.w *= inv;
                    } else {
                        v = *(const float4*)(xb + (size_t)row * D + k);
                    }
                }
                store_bf16_quad(As + m * RSTR, k, v);
            }
            __syncthreads();

            const char* Bsel = phase ? Bl : Bw;
            const int a_base = (warp_m * 32 + (lane >> 2)) * RSTR + (lane & 3) * 8;
            const int b_base = (warp_n * 64 + (lane >> 2)) * RSTR + (lane & 3) * 8;

            #pragma unroll
            for (int ks = 0; ks < 8; ks++) {
                uint2 a_f[2][2];
                #pragma unroll
                for (int mf = 0; mf < 2; mf++) {
                    const char* ap = As + a_base + mf * 16 * RSTR + ks * 32;
                    a_f[mf][0] = *(const uint2*)ap;
                    a_f[mf][1] = *(const uint2*)(ap + 8 * RSTR);
                }
                #pragma unroll
                for (int nf = 0; nf < 8; nf++) {
                    uint2 b = *(const uint2*)(Bsel + b_base + nf * 8 * RSTR + ks * 32);
                    mma_bf16(acc[0][nf], a_f[0][0].x, a_f[0][1].x,
                             a_f[0][0].y, a_f[0][1].y, b.x, b.y);
                    mma_bf16(acc[1][nf], a_f[1][0].x, a_f[1][1].x,
                             a_f[1][0].y, a_f[1][1].y, b.x, b.y);
                }
            }
        }

        #pragma unroll
        for (int mf = 0; mf < 2; mf++) {
            #pragma unroll
            for (int half = 0; half < 2; half++) {
                int row = row0 + warp_m * 32 + mf * 16 + half * 8 + (lane >> 2);
                if (row >= N) continue;
                #pragma unroll
                for (int nf = 0; nf < 8; nf++) {
                    int col = warp_n * 64 + nf * 8 + 2 * (lane & 3);
                    float v0 = acc[mf][nf][half * 2 + 0];
                    float v1 = acc[mf][nf][half * 2 + 1];
                    float2 b = *(const float2*)(xb + (size_t)row * D + col);
                    v0 = b.x + res * tanh_fast(v0);
                    v1 = b.y + res * tanh_fast(v1);
                    if (jump) {
                        float2 jv = *(const float2*)(jump + (size_t)row * D + col);
                        v0 += jw * jv.x;
                        v1 += jw * jv.y;
                    }
                    float2 o; o.x = v0; o.y = v1;
                    *(float2*)(out + (size_t)row * D + col) = o;
                }
            }
        }
    }
}

// ---------------- launcher ------------------------------------------------
extern "C" void kernel_launch(void* const* d_in, const int* in_sizes, int n_in,
                              void* d_out, int out_size)
{
    const float* emb    = (const float*)d_in[0];
    const float* change = (const float*)d_in[1];
    const float* W1     = (const float*)d_in[2];
    const float* Wl1    = (const float*)d_in[3];
    const float* rel1   = (const float*)d_in[4];
    const float* W2     = (const float*)d_in[5];
    const float* Wl2    = (const float*)d_in[6];
    const float* rel2   = (const float*)d_in[7];
    const float* res    = (const float*)d_in[8];
    const float* jw     = (const float*)d_in[9];
    const float* ewj    = (const float*)d_in[10];
    const int*   ei     = (const int*)d_in[11];
    const int*   et     = (const int*)d_in[12];
    const int*   ej     = (const int*)d_in[13];

    const int N  = in_sizes[0] / D;
    const int E  = in_sizes[12];
    const int EJ = in_sizes[10];

    float* out = (float*)d_out;

    float *agg, *agg2, *jmp, *h, *deg;
    cudaGetSymbolAddress((void**)&agg,  g_agg);
    cudaGetSymbolAddress((void**)&agg2, g_agg2);
    cudaGetSymbolAddress((void**)&jmp,  g_jump);
    cudaGetSymbolAddress((void**)&h,    g_h);
    cudaGetSymbolAddress((void**)&deg,  g_deg);

    cudaFuncSetAttribute(gemm_mma_kernel,
                         cudaFuncAttributeMaxDynamicSharedMemorySize, GEMM_SMEM);

    // 1) zero all scratch + change passthrough (one launch)
    init_kernel<<<296, 1024>>>(agg, agg2, jmp, deg, out, change, N);

    // 2) layer-1 relational scatter fused with jump scatter
    scatter_jump_kernel<<<296, 256>>>(emb, rel1, ei, et, agg, deg, E,
                                      emb, ewj, ej, jmp, EJ);

    // 3) h = emb + res*tanh((agg/deg)@W1 + emb@Wl1)
    gemm_mma_kernel<<<296, NT, GEMM_SMEM>>>(
        agg, deg, emb, W1, Wl1, res, nullptr, nullptr, h, N);

    // 4) layer-2 relational scatter (into pre-zeroed agg2)
    scatter_jump_kernel<<<296, 256>>>(h, rel2, ei, et, agg2, nullptr, E,
                                      nullptr, nullptr, nullptr, nullptr, 0);

    // 5) dchange = h + res*tanh((agg2/deg)@W2 + h@Wl2) + jw*jump
    gemm_mma_kernel<<<296, NT, GEMM_SMEM>>>(
        agg2, deg, h, W2, Wl2, res, jmp, jw, out + (size_t)N * D, N);
}

// round 7
// speedup vs baseline: 1.0534x; 1.0534x over previous
#include <cuda_runtime.h>
#include <cstdint>
#include <cstddef>

#define D 128
#define NMAX 100000

// ---------------- static device scratch (no dynamic allocs allowed) -------
__device__ float g_agg[(size_t)NMAX * D];
__device__ float g_agg2[(size_t)NMAX * D];
__device__ float g_jump[(size_t)NMAX * D];
__device__ float g_h[(size_t)NMAX * D];
__device__ float g_deg[NMAX];

// ---------------- helpers -------------------------------------------------
__device__ __forceinline__ void red4(float* p, float4 v) {
    asm volatile("red.global.add.v4.f32 [%0], {%1,%2,%3,%4};"
                 :: "l"(p), "f"(v.x), "f"(v.y), "f"(v.z), "f"(v.w) : "memory");
}

// L2-only load (bypass L1) — keeps L1 free for the small rel table
__device__ __forceinline__ float4 ldcg4(const float* p) {
    float4 v;
    asm volatile("ld.global.cg.v4.f32 {%0,%1,%2,%3}, [%4];"
                 : "=f"(v.x), "=f"(v.y), "=f"(v.z), "=f"(v.w) : "l"(p));
    return v;
}

__device__ __forceinline__ float tanh_fast(float x) {
    float y;
    asm("tanh.approx.f32 %0, %1;" : "=f"(y) : "f"(x));
    return y;
}

__device__ __forceinline__ uint32_t bf16x2(float lo, float hi) {
    uint32_t r;
    asm("cvt.rn.bf16x2.f32 %0, %1, %2;" : "=r"(r) : "f"(hi), "f"(lo));
    return r;
}

__device__ __forceinline__ void mma_bf16(float* c,
                                         uint32_t a0, uint32_t a1,
                                         uint32_t a2, uint32_t a3,
                                         uint32_t b0, uint32_t b1) {
    asm("mma.sync.aligned.m16n8k16.row.col.f32.bf16.bf16.f32 "
        "{%0,%1,%2,%3}, {%4,%5,%6,%7}, {%8,%9}, {%0,%1,%2,%3};"
        : "+f"(c[0]), "+f"(c[1]), "+f"(c[2]), "+f"(c[3])
        : "r"(a0), "r"(a1), "r"(a2), "r"(a3), "r"(b0), "r"(b1));
}

// Permuted-k bf16 row store (16-k block = 32B: order [0,1,8,9,2,3,10,11,...])
__device__ __forceinline__ void store_bf16_quad(char* rowbase, int k, float4 v) {
    char* p = rowbase + ((k >> 4) * 32) + (((k & 7) >> 1) * 8) + (((k >> 3) & 1) * 4);
    *(uint32_t*)p       = bf16x2(v.x, v.y);
    *(uint32_t*)(p + 8) = bf16x2(v.z, v.w);
}

// ---------------- scatter: agg[dst] += x[src] * rel[etype], deg count -----
// one warp per edge (proven highest-MLP structure); x via L2-only loads so
// the 200x128 rel table stays L1-resident.
__global__ void scatter_kernel(const float* __restrict__ x,
                               const float* __restrict__ rel,
                               const int* __restrict__ ei,     // [2, E]
                               const int* __restrict__ etype,  // [E]
                               float* __restrict__ agg,
                               float* __restrict__ deg,        // null on layer 2
                               int E)
{
    int e = blockIdx.x * (blockDim.x >> 5) + (threadIdx.x >> 5);
    if (e >= E) return;
    int lane = threadIdx.x & 31;
    int s = __ldg(ei + e);
    int d = __ldg(ei + E + e);
    int t = __ldg(etype + e);
    float4 xv = ldcg4(x + (size_t)s * D + lane * 4);
    float4 rv = *(const float4*)(rel + (size_t)t * D + lane * 4);  // L1-cached
    float4 m;
    m.x = xv.x * rv.x; m.y = xv.y * rv.y;
    m.z = xv.z * rv.z; m.w = xv.w * rv.w;
    red4(agg + (size_t)d * D + lane * 4, m);
    if (deg != nullptr && lane == 0)
        atomicAdd(deg + d, 1.0f);
}

// ---------------- jump: out[jdst] += w[e] * emb[jsrc] ---------------------
__global__ void jump_kernel(const float* __restrict__ emb,
                            const float* __restrict__ ew,
                            const int* __restrict__ ej,   // [2, EJ]
                            float* __restrict__ out,
                            int EJ)
{
    int e = blockIdx.x * (blockDim.x >> 5) + (threadIdx.x >> 5);
    if (e >= EJ) return;
    int lane = threadIdx.x & 31;
    int s = __ldg(ej + e);
    int d = __ldg(ej + EJ + e);
    float w = __ldg(ew + e);
    float4 xv = ldcg4(emb + (size_t)s * D + lane * 4);
    float4 m;
    m.x = xv.x * w; m.y = xv.y * w; m.z = xv.z * w; m.w = xv.w * w;
    red4(out + (size_t)d * D + lane * 4, m);
}

// ---------------- tensor-core (mma.sync bf16) fused GEMM + epilogue -------
// out[r] = xb[r] + res * tanh( (agg[r]/max(deg,1)) @ W + xb[r] @ Wl )
//          [ + jw * jump[r]  when jump != null ]
#define NT 256
#define RSTR 288
#define SM_A  0
#define SM_BW (128 * RSTR)
#define SM_BL (2 * 128 * RSTR)
#define GEMM_SMEM (3 * 128 * RSTR)    // 110592 B -> 2 CTAs/SM

__global__ __launch_bounds__(NT, 2)
void gemm_mma_kernel(const float* __restrict__ agg,
                     const float* __restrict__ deg,
                     const float* __restrict__ xb,
                     const float* __restrict__ W,
                     const float* __restrict__ Wl,
                     const float* __restrict__ res_p,
                     const float* __restrict__ jump,
                     const float* __restrict__ jw_p,
                     float* __restrict__ out,
                     int N)
{
    extern __shared__ char smem[];
    char* As = smem + SM_A;
    char* Bw = smem + SM_BW;
    char* Bl = smem + SM_BL;

    const int t    = threadIdx.x;
    const int lane = t & 31;
    const int wid  = t >> 5;
    const int warp_m = wid & 3;
    const int warp_n = wid >> 2;

    // stage both weights transposed into perm-k bf16 layout (once)
    {
        const int n = t & 127;
        const float* wsrc = (t >> 7) ? Wl : W;
        char* brow = ((t >> 7) ? Bl : Bw) + n * RSTR;
        #pragma unroll 4
        for (int k = 0; k < 128; k += 4) {
            float4 v;
            v.x = __ldg(wsrc + (k + 0) * 128 + n);
            v.y = __ldg(wsrc + (k + 1) * 128 + n);
            v.z = __ldg(wsrc + (k + 2) * 128 + n);
            v.w = __ldg(wsrc + (k + 3) * 128 + n);
            store_bf16_quad(brow, k, v);
        }
    }
    const float res = __ldg(res_p);
    const float jw  = jump ? __ldg(jw_p) : 0.0f;
    __syncthreads();

    for (int row0 = blockIdx.x * 128; row0 < N; row0 += gridDim.x * 128) {
        float acc[2][8][4];
        #pragma unroll
        for (int mf = 0; mf < 2; mf++)
            #pragma unroll
            for (int nf = 0; nf < 8; nf++)
                #pragma unroll
                for (int j = 0; j < 4; j++) acc[mf][nf][j] = 0.0f;

        #pragma unroll 1
        for (int phase = 0; phase < 2; phase++) {
            __syncthreads();
            for (int i = t * 4; i < 128 * 128; i += NT * 4) {
                int m = i >> 7, k = i & 127;
                int row = row0 + m;
                float4 v = make_float4(0.f, 0.f, 0.f, 0.f);
                if (row < N) {
                    if (phase == 0) {
                        float inv = 1.0f / fmaxf(__ldg(deg + row), 1.0f);
                        v = *(const float4*)(agg + (size_t)row * D + k);
                        v.x *= inv; v.y *= inv; v.z *= inv; v.w *= inv;
                    } else {
                        v = *(const float4*)(xb + (size_t)row * D + k);
                    }
                }
                store_bf16_quad(As + m * RSTR, k, v);
            }
            __syncthreads();

            const char* Bsel = phase ? Bl : Bw;
            const int a_base = (warp_m * 32 + (lane >> 2)) * RSTR + (lane & 3) * 8;
            const int b_base = (warp_n * 64 + (lane >> 2)) * RSTR + (lane & 3) * 8;

            #pragma unroll
            for (int ks = 0; ks < 8; ks++) {
                uint2 a_f[2][2];
                #pragma unroll
                for (int mf = 0; mf < 2; mf++) {
                    const char* ap = As + a_base + mf * 16 * RSTR + ks * 32;
                    a_f[mf][0] = *(const uint2*)ap;
                    a_f[mf][1] = *(const uint2*)(ap + 8 * RSTR);
                }
                #pragma unroll
                for (int nf = 0; nf < 8; nf++) {
                    uint2 b = *(const uint2*)(Bsel + b_base + nf * 8 * RSTR + ks * 32);
                    mma_bf16(acc[0][nf], a_f[0][0].x, a_f[0][1].x,
                             a_f[0][0].y, a_f[0][1].y, b.x, b.y);
                    mma_bf16(acc[1][nf], a_f[1][0].x, a_f[1][1].x,
                             a_f[1][0].y, a_f[1][1].y, b.x, b.y);
                }
            }
        }

        #pragma unroll
        for (int mf = 0; mf < 2; mf++) {
            #pragma unroll
            for (int half = 0; half < 2; half++) {
                int row = row0 + warp_m * 32 + mf * 16 + half * 8 + (lane >> 2);
                if (row >= N) continue;
                #pragma unroll
                for (int nf = 0; nf < 8; nf++) {
                    int col = warp_n * 64 + nf * 8 + 2 * (lane & 3);
                    float v0 = acc[mf][nf][half * 2 + 0];
                    float v1 = acc[mf][nf][half * 2 + 1];
                    float2 b = *(const float2*)(xb + (size_t)row * D + col);
                    v0 = b.x + res * tanh_fast(v0);
                    v1 = b.y + res * tanh_fast(v1);
                    if (jump) {
                        float2 jv = *(const float2*)(jump + (size_t)row * D + col);
                        v0 += jw * jv.x;
                        v1 += jw * jv.y;
                    }
                    float2 o; o.x = v0; o.y = v1;
                    *(float2*)(out + (size_t)row * D + col) = o;
                }
            }
        }
    }
}

// ---------------- launcher ------------------------------------------------
extern "C" void kernel_launch(void* const* d_in, const int* in_sizes, int n_in,
                              void* d_out, int out_size)
{
    const float* emb    = (const float*)d_in[0];
    const float* change = (const float*)d_in[1];
    const float* W1     = (const float*)d_in[2];
    const float* Wl1    = (const float*)d_in[3];
    const float* rel1   = (const float*)d_in[4];
    const float* W2     = (const float*)d_in[5];
    const float* Wl2    = (const float*)d_in[6];
    const float* rel2   = (const float*)d_in[7];
    const float* res    = (const float*)d_in[8];
    const float* jw     = (const float*)d_in[9];
    const float* ewj    = (const float*)d_in[10];
    const int*   ei     = (const int*)d_in[11];
    const int*   et     = (const int*)d_in[12];
    const int*   ej     = (const int*)d_in[13];

    const int N  = in_sizes[0] / D;
    const int E  = in_sizes[12];
    const int EJ = in_sizes[10];

    float* out = (float*)d_out;

    float *agg, *agg2, *jmp, *h, *deg;
    cudaGetSymbolAddress((void**)&agg,  g_agg);
    cudaGetSymbolAddress((void**)&agg2, g_agg2);
    cudaGetSymbolAddress((void**)&jmp,  g_jump);
    cudaGetSymbolAddress((void**)&h,    g_h);
    cudaGetSymbolAddress((void**)&deg,  g_deg);

    cudaFuncSetAttribute(gemm_mma_kernel,
                         cudaFuncAttributeMaxDynamicSharedMemorySize, GEMM_SMEM);

    const size_t nd = (size_t)N * D * sizeof(float);

    // all zeroing up front (agg2 for layer 2 -> no mid-path memset)
    cudaMemsetAsync(agg,  0, nd);
    cudaMemsetAsync(agg2, 0, nd);
    cudaMemsetAsync(jmp,  0, nd);
    cudaMemsetAsync(deg,  0, (size_t)N * sizeof(float));

    const int eb = (E + 7) / 8;
    const int jb = (EJ + 7) / 8;

    // layer 1 scatter (+ degree count) and jump scatter (independent)
    scatter_kernel<<<eb, 256>>>(emb, rel1, ei, et, agg, deg, E);
    jump_kernel<<<jb, 256>>>(emb, ewj, ej, jmp, EJ);

    // h = emb + res*tanh((agg/deg)@W1 + emb@Wl1)
    gemm_mma_kernel<<<296, NT, GEMM_SMEM>>>(
        agg, deg, emb, W1, Wl1, res, nullptr, nullptr, h, N);

    // layer 2 scatter
    scatter_kernel<<<eb, 256>>>(h, rel2, ei, et, agg2, nullptr, E);

    // dchange = h + res*tanh((agg2/deg)@W2 + h@Wl2) + jw*jump
    gemm_mma_kernel<<<296, NT, GEMM_SMEM>>>(
        agg2, deg, h, W2, Wl2, res, jmp, jw, out + (size_t)N * D, N);

    // first output: change passthrough
    cudaMemcpyAsync(out, change, nd, cudaMemcpyDeviceToDevice);
}